// round 6
// baseline (speedup 1.0000x reference)
#include <cuda_runtime.h>
#include <cstdint>

// Conv(5x5, SAME) over [256,1,512,512] + FastLIF + FastLI temporal scan.
// Tile 64x16 per block (grid 256), 128 threads; each thread computes
// 2 rows x 4 cols. Conv inner product uses packed fma.rn.f32x2 (FFMA2):
// column pairs (c,c+1) consume operand pairs (k_b,k_{b+1}) with broadcast
// (w,w) weight pairs -> half the FMA instruction count. Triple-buffered
// smem via cp.async (zfill OOB), prefetch depth 2, one barrier/timestep.

#define TT 256
#define HH 512
#define WW 512
#define HW (HH*WW)
#define TW 64        // tile width
#define THT 16       // tile height
#define NT 128       // threads per block (4 warps)
#define SWP 72       // smem row stride in floats (cols x0-4 .. x0+67)
#define SH 20        // rows y0-2 .. y0+17
#define F4R 18       // float4 per smem row
#define FILLV (SH*F4R)        // 360 float4 copies per tile
#define PF 3                  // ceil(360/128) fill slots per thread
#define BUFSZ (SH*SWP + 4)    // +4 floats scratch for inactive zfill slots
#define SCRATCH (SH*SWP)

#define ALPHA_LIF 0.85f
#define V_TH 2.0f
#define ALPHA_LI 0.9f

__device__ __forceinline__ void cp_async16(uint32_t dst_smem, const void* src, int srcsize) {
    asm volatile("cp.async.cg.shared.global [%0], [%1], 16, %2;\n"
                 :: "r"(dst_smem), "l"(src), "r"(srcsize));
}
__device__ __forceinline__ void cp_commit() {
    asm volatile("cp.async.commit_group;\n");
}
__device__ __forceinline__ void cp_wait1() {
    asm volatile("cp.async.wait_group 1;\n");
}

// ---- packed f32x2 helpers ----
__device__ __forceinline__ uint64_t pk2(float lo, float hi) {
    uint64_t r;
    asm("mov.b64 %0, {%1, %2};" : "=l"(r) : "f"(lo), "f"(hi));
    return r;
}
__device__ __forceinline__ void unpk2(uint64_t p, float& lo, float& hi) {
    asm("mov.b64 {%0, %1}, %2;" : "=f"(lo), "=f"(hi) : "l"(p));
}
__device__ __forceinline__ void fma2(uint64_t& acc, uint64_t w, uint64_t k) {
    asm("fma.rn.f32x2 %0, %1, %2, %0;" : "+l"(acc) : "l"(w), "l"(k));
}

__global__ __launch_bounds__(NT, 2)
void snn_fused_kernel(const float* __restrict__ x,
                      const float* __restrict__ kern,
                      float* __restrict__ out)
{
    __shared__ float sm[3][BUFSZ];

    const int tid = threadIdx.x;
    const int x0 = blockIdx.x * TW;
    const int y0 = blockIdx.y * THT;
    const int tc = tid & 15;          // col group: output cols x0+4tc .. +3
    const int rg = tid >> 4;          // row-pair group: output rows y0+2rg, y0+2rg+1

    // 5x5 weights, broadcast into (w,w) pairs for FFMA2
    uint64_t wp[25];
#pragma unroll
    for (int i = 0; i < 25; i++) {
        float w = __ldg(kern + i);
        wp[i] = pk2(w, w);
    }

    // ---- Precompute the PF cp.async fill slots (loop-invariant across t) ----
    int soff[PF], goff[PF], ssz[PF];
#pragma unroll
    for (int j = 0; j < PF; j++) {
        int i = tid + j * NT;
        if (i < FILLV) {
            int rr = i / F4R;
            int c4 = i - rr * F4R;
            int gy = y0 - 2 + rr;
            int gx = x0 - 4 + 4 * c4;
            bool v = (gy >= 0) && (gy < HH) && (gx >= 0) && (gx <= WW - 4);
            soff[j] = rr * SWP + 4 * c4;
            goff[j] = v ? (gy * WW + gx) : 0;
            ssz[j]  = v ? 16 : 0;
        } else {
            soff[j] = SCRATCH;
            goff[j] = 0;
            ssz[j]  = 0;
        }
    }

    uint32_t c0 = (uint32_t)__cvta_generic_to_shared(&sm[0][0]);
    uint32_t c1 = (uint32_t)__cvta_generic_to_shared(&sm[1][0]);
    uint32_t c2 = (uint32_t)__cvta_generic_to_shared(&sm[2][0]);
    int bi = 0;   // front (read) buffer index

    // ---- Prefetch timesteps 0 and 1 ----
    {
        const float* xt = x;
#pragma unroll
        for (int j = 0; j < PF; j++) cp_async16(c0 + 4u * soff[j], xt + goff[j], ssz[j]);
        cp_commit();
        xt += HW;
#pragma unroll
        for (int j = 0; j < PF; j++) cp_async16(c1 + 4u * soff[j], xt + goff[j], ssz[j]);
        cp_commit();
    }

    // LIF / LI state: 2 rows x 4 cols
    float s1[8], s2[8];
#pragma unroll
    for (int i = 0; i < 8; i++) { s1[i] = 0.f; s2[i] = 0.f; }

    const float* xp = x + 2 * (size_t)HW;                        // source for t+2
    float* op = out + (size_t)(y0 + 2 * rg) * WW + x0 + 4 * tc;  // row 0 of pair
    const int rbase = (2 * rg) * SWP + 4 * tc;                   // smem read base

    for (int t = 0; t < TT; t++) {
        cp_wait1();
        __syncthreads();

        // Prefetch t+2 into the freed buffer (c2)
        if (t + 2 < TT) {
#pragma unroll
            for (int j = 0; j < PF; j++)
                cp_async16(c2 + 4u * soff[j], xp + goff[j], ssz[j]);
        }
        cp_commit();
        xp += HW;

        // ---- 5x5 conv, packed: 2 output rows x 2 col-pairs ----
        const float* rb = &sm[bi][0] + rbase;

        uint64_t A01 = 0ull, A23 = 0ull;   // output row 2rg,   cols (0,1) (2,3)
        uint64_t D01 = 0ull, D23 = 0ull;   // output row 2rg+1, cols (0,1) (2,3)
#pragma unroll
        for (int j = 0; j < 6; j++) {
            const float* rp = rb + j * SWP;
            float2 u  = *(const float2*)(rp + 2);   // k0,k1
            float4 v4 = *(const float4*)(rp + 4);   // k2..k5
            float2 w2 = *(const float2*)(rp + 8);   // k6,k7
            // aligned pairs (free) + 3 odd pairs (packed)
            uint64_t E0 = pk2(u.x,  u.y);   // (k0,k1)
            uint64_t E1 = pk2(v4.x, v4.y);  // (k2,k3)
            uint64_t E2 = pk2(v4.z, v4.w);  // (k4,k5)
            uint64_t E3 = pk2(w2.x, w2.y);  // (k6,k7)
            uint64_t O0 = pk2(u.y,  v4.x);  // (k1,k2)
            uint64_t O1 = pk2(v4.y, v4.z);  // (k3,k4)
            uint64_t O2 = pk2(v4.w, w2.x);  // (k5,k6)
            // operand pair for tap b: cols(0,1) -> (k_b,k_{b+1}); cols(2,3) -> (k_{b+2},k_{b+3})
            uint64_t p01[5] = {E0, O0, E1, O1, E2};
            uint64_t p23[5] = {E1, O1, E2, O2, E3};
            if (j < 5) {                     // contributes to row 2rg, tap a=j
                const uint64_t* wa = wp + j * 5;
#pragma unroll
                for (int b = 0; b < 5; b++) {
                    fma2(A01, wa[b], p01[b]);
                    fma2(A23, wa[b], p23[b]);
                }
            }
            if (j > 0) {                     // contributes to row 2rg+1, tap a=j-1
                const uint64_t* wb = wp + (j - 1) * 5;
#pragma unroll
                for (int b = 0; b < 5; b++) {
                    fma2(D01, wb[b], p01[b]);
                    fma2(D23, wb[b], p23[b]);
                }
            }
        }

        // ---- LIF fire + soft reset, LI readout (scalar) ----
        float acc[8];
        unpk2(A01, acc[0], acc[1]);
        unpk2(A23, acc[2], acc[3]);
        unpk2(D01, acc[4], acc[5]);
        unpk2(D23, acc[6], acc[7]);

        float o[8];
#pragma unroll
        for (int i = 0; i < 8; i++) {
            float v = fmaf(ALPHA_LIF, s1[i], acc[i]);
            float spk = (v >= V_TH) ? 1.0f : 0.0f;
            s1[i] = fmaf(spk, -V_TH, v);
            s2[i] = fmaf(ALPHA_LI, s2[i], spk);
            o[i] = s2[i];
        }
        float4 o0 = {o[0], o[1], o[2], o[3]};
        float4 o1 = {o[4], o[5], o[6], o[7]};
        *(float4*)op = o0;
        *(float4*)(op + WW) = o1;
        op += HW;

        // Rotate buffers
        uint32_t tb = c0; c0 = c1; c1 = c2; c2 = tb;
        bi = (bi == 2) ? 0 : bi + 1;
    }
}

extern "C" void kernel_launch(void* const* d_in, const int* in_sizes, int n_in,
                              void* d_out, int out_size)
{
    const float* x = (const float*)d_in[0];
    const float* k = (const float*)d_in[1];
    if (in_sizes[0] == 25) {  // defensive: swap if metadata order differs
        const float* tmp = x; x = k; k = tmp;
    }
    float* out = (float*)d_out;

    dim3 grid(WW / TW, HH / THT);   // 8 x 32 = 256 blocks
    snn_fused_kernel<<<grid, NT>>>(x, k, out);
}

// round 8
// speedup vs baseline: 1.1117x; 1.1117x over previous
#include <cuda_runtime.h>
#include <cstdint>

// Conv(5x5, SAME) over [256,1,512,512] + FastLIF + FastLI temporal scan.
// Tile 64x16 per block (grid 256), 128 threads. WARP-AUTONOMOUS: each warp
// owns a 32x8 output quadrant with a private triple-buffered smem region
// (12 rows x 40 cols incl. halo) filled by its own cp.async slots.
// Synchronization is cp.async.wait_group + __syncwarp() ONLY — no
// __syncthreads anywhere, so warps pipeline independently across timesteps.
// Each thread computes 2 rows x 4 cols; LIF/LI state in registers.
// Inactive zfill slots dump into per-buffer padding (rotation-safe).

#define TT 256
#define HH 512
#define WW 512
#define HW (HH*WW)
#define TW 64        // block tile width
#define THT 16       // block tile height
#define NT 128       // threads per block (4 warps)

#define QW 32        // warp quadrant width (outputs)
#define QH 8         // warp quadrant height (outputs)
#define SWP 40       // warp smem row stride (32+8 halo cols)
#define SHR 12       // warp smem rows (8+4 halo)
#define WBUF (SHR*SWP)        // 480 floats used per buffer
#define WBUFP (WBUF + 4)      // +4 floats per-buffer scratch (zfill dump)
#define F4R 10                // float4 per smem row
#define FILLV (SHR*F4R)       // 120 float4 copies per warp tile
#define PF 4                  // ceil(120/32) fill slots per lane

#define ALPHA_LIF 0.85f
#define V_TH 2.0f
#define ALPHA_LI 0.9f

__device__ __forceinline__ void cp_async16(uint32_t dst_smem, const void* src, int srcsize) {
    asm volatile("cp.async.cg.shared.global [%0], [%1], 16, %2;\n"
                 :: "r"(dst_smem), "l"(src), "r"(srcsize));
}
__device__ __forceinline__ void cp_commit() {
    asm volatile("cp.async.commit_group;\n");
}
__device__ __forceinline__ void cp_wait1() {
    asm volatile("cp.async.wait_group 1;\n");
}

__global__ __launch_bounds__(NT, 2)
void snn_fused_kernel(const float* __restrict__ x,
                      const float* __restrict__ kern,
                      float* __restrict__ out)
{
    // [warp][3 buffers][WBUFP floats each]
    __shared__ __align__(16) float sm[4 * 3 * WBUFP];

    const int tid  = threadIdx.x;
    const int w    = tid >> 5;        // warp 0..3
    const int lane = tid & 31;
    const int wx   = w & 1;           // quadrant col (0,1)
    const int wy   = w >> 1;          // quadrant row (0,1)
    const int tc   = lane & 7;        // col group: 4 cols each
    const int rgL  = lane >> 3;       // row-pair group 0..3

    const int x0 = blockIdx.x * TW + QW * wx;   // quadrant origin
    const int y0 = blockIdx.y * THT + QH * wy;

    // 5x5 weights in registers (uniform broadcast)
    float wgt[25];
#pragma unroll
    for (int i = 0; i < 25; i++) wgt[i] = __ldg(kern + i);

    // ---- Precompute this lane's PF cp.async fill slots (invariant over t) ----
    // Slot j copies float4 #(lane + j*32) of the 12-row x 10-float4 warp tile.
    // smem col 0 <-> global col x0-4 ; smem row 0 <-> global row y0-2.
    // Offsets are RELATIVE TO THE BUFFER BASE; inactive slots target the
    // per-buffer scratch at offset WBUF (valid for any rotated buffer).
    int soff[PF], goff[PF], ssz[PF];
#pragma unroll
    for (int j = 0; j < PF; j++) {
        int i = lane + j * 32;
        if (i < FILLV) {
            int rr = i / F4R;
            int c4 = i - rr * F4R;
            int gy = y0 - 2 + rr;
            int gx = x0 - 4 + 4 * c4;
            bool v = (gy >= 0) && (gy < HH) && (gx >= 0) && (gx <= WW - 4);
            soff[j] = rr * SWP + 4 * c4;
            goff[j] = v ? (gy * WW + gx) : 0;
            ssz[j]  = v ? 16 : 0;
        } else {
            soff[j] = WBUF;   // per-buffer scratch, rotation-safe
            goff[j] = 0;
            ssz[j]  = 0;
        }
    }

    // Per-warp buffer base addresses (u32 smem space), rotated each step
    const int wbase = w * 3 * WBUFP;
    uint32_t c0 = (uint32_t)__cvta_generic_to_shared(&sm[wbase]);
    uint32_t c1 = c0 + 4u * WBUFP;
    uint32_t c2 = c0 + 8u * WBUFP;
    int bo = 0;                        // front buffer float-offset within warp region

    // ---- Prefetch timesteps 0 and 1 ----
    {
        const float* xt = x;
#pragma unroll
        for (int j = 0; j < PF; j++) cp_async16(c0 + 4u * soff[j], xt + goff[j], ssz[j]);
        cp_commit();
        xt += HW;
#pragma unroll
        for (int j = 0; j < PF; j++) cp_async16(c1 + 4u * soff[j], xt + goff[j], ssz[j]);
        cp_commit();
    }

    // LIF / LI state: 2 rows x 4 cols
    float s1[8], s2[8];
#pragma unroll
    for (int i = 0; i < 8; i++) { s1[i] = 0.f; s2[i] = 0.f; }

    const float* xp = x + 2 * (size_t)HW;                         // source for t+2
    float* op = out + (size_t)(y0 + 2 * rgL) * WW + x0 + 4 * tc;  // row 0 of pair
    const int rbase = wbase + (2 * rgL) * SWP + 4 * tc;           // smem read base

    for (int t = 0; t < TT; t++) {
        cp_wait1();      // this lane's copies for step t have landed
        __syncwarp();    // other lanes' copies visible; all lanes past t-1 reads

        // Prefetch t+2 into the freed buffer (c2)
        if (t + 2 < TT) {
#pragma unroll
            for (int j = 0; j < PF; j++)
                cp_async16(c2 + 4u * soff[j], xp + goff[j], ssz[j]);
        }
        cp_commit();     // unconditional: uniform wait_group accounting
        xp += HW;

        // ---- 5x5 conv: 2 output rows x 4 cols from 6 streamed input rows ----
        // Row loads: 3x LDS.128 (cols 0..11 of the 12-wide window), all
        // 16B-aligned, conflict-free; window uses cols 2..9.
        const float* rb = &sm[rbase + bo];

        float a0 = 0.f, a1 = 0.f, a2 = 0.f, a3 = 0.f;   // output row 2rgL
        float d0 = 0.f, d1 = 0.f, d2 = 0.f, d3 = 0.f;   // output row 2rgL+1
#pragma unroll
        for (int j = 0; j < 6; j++) {
            const float* rp = rb + j * SWP;
            float4 q0 = *(const float4*)(rp + 0);
            float4 q1 = *(const float4*)(rp + 4);
            float4 q2 = *(const float4*)(rp + 8);
            float m0 = q0.z, m1 = q0.w, m2 = q1.x, m3 = q1.y;
            float m4 = q1.z, m5 = q1.w, m6 = q2.x, m7 = q2.y;
            if (j < 5) {                     // row 2rgL, vertical tap a=j
                const float* wa = wgt + j * 5;
                a0 = fmaf(wa[0], m0, a0); a0 = fmaf(wa[1], m1, a0);
                a0 = fmaf(wa[2], m2, a0); a0 = fmaf(wa[3], m3, a0);
                a0 = fmaf(wa[4], m4, a0);
                a1 = fmaf(wa[0], m1, a1); a1 = fmaf(wa[1], m2, a1);
                a1 = fmaf(wa[2], m3, a1); a1 = fmaf(wa[3], m4, a1);
                a1 = fmaf(wa[4], m5, a1);
                a2 = fmaf(wa[0], m2, a2); a2 = fmaf(wa[1], m3, a2);
                a2 = fmaf(wa[2], m4, a2); a2 = fmaf(wa[3], m5, a2);
                a2 = fmaf(wa[4], m6, a2);
                a3 = fmaf(wa[0], m3, a3); a3 = fmaf(wa[1], m4, a3);
                a3 = fmaf(wa[2], m5, a3); a3 = fmaf(wa[3], m6, a3);
                a3 = fmaf(wa[4], m7, a3);
            }
            if (j > 0) {                     // row 2rgL+1, vertical tap a=j-1
                const float* wb = wgt + (j - 1) * 5;
                d0 = fmaf(wb[0], m0, d0); d0 = fmaf(wb[1], m1, d0);
                d0 = fmaf(wb[2], m2, d0); d0 = fmaf(wb[3], m3, d0);
                d0 = fmaf(wb[4], m4, d0);
                d1 = fmaf(wb[0], m1, d1); d1 = fmaf(wb[1], m2, d1);
                d1 = fmaf(wb[2], m3, d1); d1 = fmaf(wb[3], m4, d1);
                d1 = fmaf(wb[4], m5, d1);
                d2 = fmaf(wb[0], m2, d2); d2 = fmaf(wb[1], m3, d2);
                d2 = fmaf(wb[2], m4, d2); d2 = fmaf(wb[3], m5, d2);
                d2 = fmaf(wb[4], m6, d2);
                d3 = fmaf(wb[0], m3, d3); d3 = fmaf(wb[1], m4, d3);
                d3 = fmaf(wb[2], m5, d3); d3 = fmaf(wb[3], m6, d3);
                d3 = fmaf(wb[4], m7, d3);
            }
        }

        // ---- LIF fire + soft reset, LI readout, two vector stores ----
        float acc[8] = {a0, a1, a2, a3, d0, d1, d2, d3};
        float o[8];
#pragma unroll
        for (int i = 0; i < 8; i++) {
            float v = fmaf(ALPHA_LIF, s1[i], acc[i]);
            float spk = (v >= V_TH) ? 1.0f : 0.0f;
            s1[i] = fmaf(spk, -V_TH, v);
            s2[i] = fmaf(ALPHA_LI, s2[i], spk);
            o[i] = s2[i];
        }
        float4 o0 = {o[0], o[1], o[2], o[3]};
        float4 o1 = {o[4], o[5], o[6], o[7]};
        *(float4*)op = o0;
        *(float4*)(op + WW) = o1;
        op += HW;

        // Rotate this warp's buffers (addresses and read offset together)
        uint32_t tb = c0; c0 = c1; c1 = c2; c2 = tb;
        bo += WBUFP; if (bo == 3 * WBUFP) bo = 0;
    }
}

extern "C" void kernel_launch(void* const* d_in, const int* in_sizes, int n_in,
                              void* d_out, int out_size)
{
    const float* x = (const float*)d_in[0];
    const float* k = (const float*)d_in[1];
    if (in_sizes[0] == 25) {  // defensive: swap if metadata order differs
        const float* tmp = x; x = k; k = tmp;
    }
    float* out = (float*)d_out;

    dim3 grid(WW / TW, HH / THT);   // 8 x 32 = 256 blocks
    snn_fused_kernel<<<grid, NT>>>(x, k, out);
}